// round 8
// baseline (speedup 1.0000x reference)
#include <cuda_runtime.h>
#include <cuda_bf16.h>

// VolumeSDFRenderer: R=65536 rays, N=128 samples.
// inputs (metadata order): distance [R,N] f32, color [R,N,3] f32, depth_values [R,N] f32
// output: concat(out_color [R,3], geometry zeros [R,N,3]) as f32.
//
// Single fused kernel, one warp per ray. Lane k owns samples [4k, 4k+4).
// Plain (default-policy) float4 loads front-batched for MLP; __ldcs/__stcs
// hints REMOVED (measured -1.2us kernel regression in R6 — L2 write absorption
// of the zero stream is beneficial, evict-first defeats it).
// Warp-shuffle exclusive scan (shift of inclusive — avoids FAR_DELTA
// cancellation in lane 31). Transmittance advanced by telescoping products
// (5 MUFU exps instead of 8). shfl_xor color reduction.

#define ALPHA 10.0f
#define INV_BETA 20.0f      // 1/0.05
#define FAR_DELTA 1e10f

__device__ __forceinline__ float sdf_density(float dist) {
    float s = -dist;
    float e = __expf(-INV_BETA * fabsf(s));
    // s<=0: alpha*0.5*exp(s/beta) = 5*e ; s>0: alpha*(1-0.5*exp(-s/beta)) = 10 - 5*e
    return (s <= 0.0f) ? (0.5f * ALPHA * e) : (ALPHA - 0.5f * ALPHA * e);
}

__global__ __launch_bounds__(256, 8)
void volume_sdf_fused_kernel(const float* __restrict__ distance,
                             const float* __restrict__ color,
                             const float* __restrict__ depth,
                             float* __restrict__ out,          // full output buffer
                             int n_rays)
{
    const int warp_id = (blockIdx.x * blockDim.x + threadIdx.x) >> 5;
    const int lane    = threadIdx.x & 31;
    if (warp_id >= n_rays) return;
    const int ray = warp_id;

    const size_t base128 = (size_t)ray * 128;

    // ---- front-batched loads: 5 independent float4 LDGs (default policy) ----
    const float4 d4 = reinterpret_cast<const float4*>(distance + base128)[lane];
    const float4 t4 = reinterpret_cast<const float4*>(depth    + base128)[lane];
    const float4* cp = reinterpret_cast<const float4*>(color + (size_t)ray * 384) + lane * 3;
    const float4 ca = cp[0];
    const float4 cb = cp[1];
    const float4 cc = cp[2];

    // ---- zero this ray's geometry slab: 384 floats = 96 float4, coalesced ----
    {
        float4* geo = reinterpret_cast<float4*>(out + (size_t)n_rays * 3 + (size_t)ray * 384);
        const float4 z = make_float4(0.f, 0.f, 0.f, 0.f);
        geo[lane]      = z;
        geo[lane + 32] = z;
        geo[lane + 64] = z;
    }

    // ---- deltas: need t[4k+4] = next lane's t4.x ----
    float t_next = __shfl_down_sync(0xffffffffu, t4.x, 1);
    float dlt0 = t4.y - t4.x;
    float dlt1 = t4.z - t4.y;
    float dlt2 = t4.w - t4.z;
    float dlt3 = (lane == 31) ? FAR_DELTA : (t_next - t4.w);

    // ---- d = density * delta ----
    float dd0 = sdf_density(d4.x) * dlt0;
    float dd1 = sdf_density(d4.y) * dlt1;
    float dd2 = sdf_density(d4.z) * dlt2;
    float dd3 = sdf_density(d4.w) * dlt3;

    // ---- per-sample attenuation factors (reused for weights AND transmittance) ----
    float a0 = __expf(-dd0);
    float a1 = __expf(-dd1);
    float a2 = __expf(-dd2);
    float a3 = __expf(-dd3);

    // ---- warp exclusive scan of lane sums (for cross-lane transmittance) ----
    float lane_sum = dd0 + dd1 + dd2 + dd3;
    float x = lane_sum;
    #pragma unroll
    for (int off = 1; off < 32; off <<= 1) {
        float y = __shfl_up_sync(0xffffffffu, x, off);
        if (lane >= off) x += y;
    }
    // exclusive prefix = previous lane's inclusive value (exact; avoids
    // subtracting lane 31's huge FAR_DELTA-contaminated lane_sum)
    float excl = __shfl_up_sync(0xffffffffu, x, 1);
    if (lane == 0) excl = 0.0f;

    // ---- transmittance telescoping: T_{i+1} = T_i * a_i ----
    float T0 = __expf(-excl);
    float T1 = T0 * a0;
    float T2 = T1 * a1;
    float T3 = T2 * a2;

    float w0 = (1.0f - a0) * T0;
    float w1 = (1.0f - a1) * T1;
    float w2 = (1.0f - a2) * T2;
    float w3 = (1.0f - a3) * T3;

    // unpack 12 floats -> 4 rgb samples
    float r = w0 * ca.x + w1 * ca.w + w2 * cb.z + w3 * cc.y;
    float g = w0 * ca.y + w1 * cb.x + w2 * cb.w + w3 * cc.z;
    float b = w0 * ca.z + w1 * cb.y + w2 * cc.x + w3 * cc.w;

    // ---- warp reduction ----
    #pragma unroll
    for (int off = 16; off >= 1; off >>= 1) {
        r += __shfl_xor_sync(0xffffffffu, r, off);
        g += __shfl_xor_sync(0xffffffffu, g, off);
        b += __shfl_xor_sync(0xffffffffu, b, off);
    }

    if (lane == 0) {
        out[(size_t)ray * 3 + 0] = r;
        out[(size_t)ray * 3 + 1] = g;
        out[(size_t)ray * 3 + 2] = b;
    }
}

extern "C" void kernel_launch(void* const* d_in, const int* in_sizes, int n_in,
                              void* d_out, int out_size)
{
    const float* distance = (const float*)d_in[0];
    const float* color    = (const float*)d_in[1];
    const float* depth    = (const float*)d_in[2];
    float* out = (float*)d_out;

    const int n_rays = in_sizes[0] / 128;   // R = 65536

    // one warp per ray; 256 threads = 8 warps per block
    const int warps_per_block = 8;
    const int blocks = (n_rays + warps_per_block - 1) / warps_per_block;
    volume_sdf_fused_kernel<<<blocks, 256>>>(distance, color, depth, out, n_rays);
}

// round 9
// speedup vs baseline: 1.1113x; 1.1113x over previous
#include <cuda_runtime.h>
#include <cuda_bf16.h>

// VolumeSDFRenderer: R=65536 rays, N=128 samples.
// inputs (metadata order): distance [R,N] f32, color [R,N,3] f32, depth_values [R,N] f32
// output: concat(out_color [R,3], geometry zeros [R,N,3]) as f32.
//
// Single fused kernel, one warp per ray. Lane k owns samples [4k, 4k+4).
// KEY OPTIMIZATION (this round): transmittance-based color-load culling.
// The warp scan over density*delta is computed from distance+depth FIRST; a
// lane whose starting transmittance T0 = exp(-excl_prefix) < T_EPS contributes
// total weight <= T0 <= 1e-5 (weights from that point on sum to exactly T0),
// so its 3 color float4 loads are SKIPPED. Dead lanes are a contiguous warp
// tail (T is monotone), so those DRAM sectors are never fetched — cuts the
// 100MB color read stream by the fraction of saturated samples (~40-50%).
// Induced rel-err <= ~2e-5, far under the 1e-3 threshold.
//
// Also: exclusive scan via shift-of-inclusive (avoids FAR_DELTA cancellation
// in lane 31), telescoping transmittance (5 exps / lane), geometry zeros
// written by the same warp (coalesced float4 stores), plain cache policy
// (__ldcs/__stcs measured as a regression in R6).

#define ALPHA 10.0f
#define INV_BETA 20.0f      // 1/0.05
#define FAR_DELTA 1e10f
#define T_EPS 1e-5f

__device__ __forceinline__ float sdf_density(float dist) {
    float s = -dist;
    float e = __expf(-INV_BETA * fabsf(s));
    // s<=0: alpha*0.5*exp(s/beta) = 5*e ; s>0: alpha*(1-0.5*exp(-s/beta)) = 10 - 5*e
    return (s <= 0.0f) ? (0.5f * ALPHA * e) : (ALPHA - 0.5f * ALPHA * e);
}

__global__ __launch_bounds__(256, 8)
void volume_sdf_fused_kernel(const float* __restrict__ distance,
                             const float* __restrict__ color,
                             const float* __restrict__ depth,
                             float* __restrict__ out,          // full output buffer
                             int n_rays)
{
    const int warp_id = (blockIdx.x * blockDim.x + threadIdx.x) >> 5;
    const int lane    = threadIdx.x & 31;
    if (warp_id >= n_rays) return;
    const int ray = warp_id;

    const size_t base128 = (size_t)ray * 128;

    // ---- front-batched scan inputs: distance + depth ----
    const float4 d4 = reinterpret_cast<const float4*>(distance + base128)[lane];
    const float4 t4 = reinterpret_cast<const float4*>(depth    + base128)[lane];

    // ---- zero this ray's geometry slab: 384 floats = 96 float4, coalesced ----
    {
        float4* geo = reinterpret_cast<float4*>(out + (size_t)n_rays * 3 + (size_t)ray * 384);
        const float4 z = make_float4(0.f, 0.f, 0.f, 0.f);
        geo[lane]      = z;
        geo[lane + 32] = z;
        geo[lane + 64] = z;
    }

    // ---- deltas: need t[4k+4] = next lane's t4.x ----
    float t_next = __shfl_down_sync(0xffffffffu, t4.x, 1);
    float dlt0 = t4.y - t4.x;
    float dlt1 = t4.z - t4.y;
    float dlt2 = t4.w - t4.z;
    float dlt3 = (lane == 31) ? FAR_DELTA : (t_next - t4.w);

    // ---- d = density * delta ----
    float dd0 = sdf_density(d4.x) * dlt0;
    float dd1 = sdf_density(d4.y) * dlt1;
    float dd2 = sdf_density(d4.z) * dlt2;
    float dd3 = sdf_density(d4.w) * dlt3;

    // ---- warp exclusive scan of lane sums (cross-lane transmittance) ----
    float lane_sum = dd0 + dd1 + dd2 + dd3;
    float x = lane_sum;
    #pragma unroll
    for (int off = 1; off < 32; off <<= 1) {
        float y = __shfl_up_sync(0xffffffffu, x, off);
        if (lane >= off) x += y;
    }
    // exclusive prefix = previous lane's inclusive value (exact; avoids
    // subtracting lane 31's huge FAR_DELTA-contaminated lane_sum)
    float excl = __shfl_up_sync(0xffffffffu, x, 1);
    if (lane == 0) excl = 0.0f;

    // ---- starting transmittance for this lane ----
    float T0 = __expf(-excl);

    float r = 0.0f, g = 0.0f, b = 0.0f;

    // ---- culled color path: lanes with T0 < T_EPS contribute < 1e-5 total ----
    if (T0 >= T_EPS) {
        const float4* cp = reinterpret_cast<const float4*>(color + (size_t)ray * 384) + lane * 3;
        const float4 ca = cp[0];
        const float4 cb = cp[1];
        const float4 cc = cp[2];

        // per-sample attenuation, telescoping transmittance
        float a0 = __expf(-dd0);
        float a1 = __expf(-dd1);
        float a2 = __expf(-dd2);
        float a3 = __expf(-dd3);
        float T1 = T0 * a0;
        float T2 = T1 * a1;
        float T3 = T2 * a2;

        float w0 = (1.0f - a0) * T0;
        float w1 = (1.0f - a1) * T1;
        float w2 = (1.0f - a2) * T2;
        float w3 = (1.0f - a3) * T3;

        // unpack 12 floats -> 4 rgb samples
        r = w0 * ca.x + w1 * ca.w + w2 * cb.z + w3 * cc.y;
        g = w0 * ca.y + w1 * cb.x + w2 * cb.w + w3 * cc.z;
        b = w0 * ca.z + w1 * cb.y + w2 * cc.x + w3 * cc.w;
    }

    // ---- warp reduction ----
    #pragma unroll
    for (int off = 16; off >= 1; off >>= 1) {
        r += __shfl_xor_sync(0xffffffffu, r, off);
        g += __shfl_xor_sync(0xffffffffu, g, off);
        b += __shfl_xor_sync(0xffffffffu, b, off);
    }

    if (lane == 0) {
        out[(size_t)ray * 3 + 0] = r;
        out[(size_t)ray * 3 + 1] = g;
        out[(size_t)ray * 3 + 2] = b;
    }
}

extern "C" void kernel_launch(void* const* d_in, const int* in_sizes, int n_in,
                              void* d_out, int out_size)
{
    const float* distance = (const float*)d_in[0];
    const float* color    = (const float*)d_in[1];
    const float* depth    = (const float*)d_in[2];
    float* out = (float*)d_out;

    const int n_rays = in_sizes[0] / 128;   // R = 65536

    // one warp per ray; 256 threads = 8 warps per block
    const int warps_per_block = 8;
    const int blocks = (n_rays + warps_per_block - 1) / warps_per_block;
    volume_sdf_fused_kernel<<<blocks, 256>>>(distance, color, depth, out, n_rays);
}

// round 10
// speedup vs baseline: 1.1643x; 1.0477x over previous
#include <cuda_runtime.h>
#include <cuda_bf16.h>

// VolumeSDFRenderer: R=65536 rays, N=128 samples.
// inputs (metadata order): distance [R,N] f32, color [R,N,3] f32, depth_values [R,N] f32
// output: concat(out_color [R,3], geometry zeros [R,N,3]) as f32.
//
// Single fused kernel, one warp per ray. Lane k owns samples [4k, 4k+4).
// Transmittance-based color-load culling: the warp scan over density*delta is
// computed from distance+depth FIRST; a lane whose starting transmittance
// T0 = exp(-excl_prefix) < T_EPS contributes total weight <= T0 (the weights
// from that point on sum to exactly T0), so its 3 color float4 loads and all
// its math are SKIPPED. Dead lanes are a contiguous warp tail (T monotone), so
// those DRAM sectors are never fetched.
// T_EPS calibration: measured rel_err 6.8e-6 @ T_EPS=1e-5 (R9); error scales
// ~linearly with T_EPS -> 3e-4 predicts ~2e-4, 5x under the 1e-3 threshold.
// (If a re-bench shows rel_err > 5e-4, fall back to 1e-4.)
//
// Also: exclusive scan via shift-of-inclusive (avoids FAR_DELTA cancellation
// in lane 31), telescoping transmittance, geometry zeros written by the same
// warp (coalesced float4 stores), plain cache policy (__ldcs/__stcs measured
// as a regression in R6).

#define ALPHA 10.0f
#define INV_BETA 20.0f      // 1/0.05
#define FAR_DELTA 1e10f
#define T_EPS 3e-4f

__device__ __forceinline__ float sdf_density(float dist) {
    float s = -dist;
    float e = __expf(-INV_BETA * fabsf(s));
    // s<=0: alpha*0.5*exp(s/beta) = 5*e ; s>0: alpha*(1-0.5*exp(-s/beta)) = 10 - 5*e
    return (s <= 0.0f) ? (0.5f * ALPHA * e) : (ALPHA - 0.5f * ALPHA * e);
}

__global__ __launch_bounds__(256, 8)
void volume_sdf_fused_kernel(const float* __restrict__ distance,
                             const float* __restrict__ color,
                             const float* __restrict__ depth,
                             float* __restrict__ out,          // full output buffer
                             int n_rays)
{
    const int warp_id = (blockIdx.x * blockDim.x + threadIdx.x) >> 5;
    const int lane    = threadIdx.x & 31;
    if (warp_id >= n_rays) return;
    const int ray = warp_id;

    const size_t base128 = (size_t)ray * 128;

    // ---- front-batched scan inputs: distance + depth ----
    const float4 d4 = reinterpret_cast<const float4*>(distance + base128)[lane];
    const float4 t4 = reinterpret_cast<const float4*>(depth    + base128)[lane];

    // ---- zero this ray's geometry slab: 384 floats = 96 float4, coalesced ----
    {
        float4* geo = reinterpret_cast<float4*>(out + (size_t)n_rays * 3 + (size_t)ray * 384);
        const float4 z = make_float4(0.f, 0.f, 0.f, 0.f);
        geo[lane]      = z;
        geo[lane + 32] = z;
        geo[lane + 64] = z;
    }

    // ---- deltas: need t[4k+4] = next lane's t4.x ----
    float t_next = __shfl_down_sync(0xffffffffu, t4.x, 1);
    float dlt0 = t4.y - t4.x;
    float dlt1 = t4.z - t4.y;
    float dlt2 = t4.w - t4.z;
    float dlt3 = (lane == 31) ? FAR_DELTA : (t_next - t4.w);

    // ---- d = density * delta ----
    float dd0 = sdf_density(d4.x) * dlt0;
    float dd1 = sdf_density(d4.y) * dlt1;
    float dd2 = sdf_density(d4.z) * dlt2;
    float dd3 = sdf_density(d4.w) * dlt3;

    // ---- warp exclusive scan of lane sums (cross-lane transmittance) ----
    float lane_sum = dd0 + dd1 + dd2 + dd3;
    float x = lane_sum;
    #pragma unroll
    for (int off = 1; off < 32; off <<= 1) {
        float y = __shfl_up_sync(0xffffffffu, x, off);
        if (lane >= off) x += y;
    }
    // exclusive prefix = previous lane's inclusive value (exact; avoids
    // subtracting lane 31's huge FAR_DELTA-contaminated lane_sum)
    float excl = __shfl_up_sync(0xffffffffu, x, 1);
    if (lane == 0) excl = 0.0f;

    float r = 0.0f, g = 0.0f, b = 0.0f;

    // ---- culled color path: cumsum > -ln(T_EPS) => contribution < T_EPS ----
    // (compare in log space: avoids computing exp for dead lanes)
    if (excl < 8.112f) {               // -ln(3e-4) = 8.1117
        float T0 = __expf(-excl);

        const float4* cp = reinterpret_cast<const float4*>(color + (size_t)ray * 384) + lane * 3;
        const float4 ca = cp[0];
        const float4 cb = cp[1];
        const float4 cc = cp[2];

        // per-sample attenuation, telescoping transmittance
        float a0 = __expf(-dd0);
        float a1 = __expf(-dd1);
        float a2 = __expf(-dd2);
        float a3 = __expf(-dd3);
        float T1 = T0 * a0;
        float T2 = T1 * a1;
        float T3 = T2 * a2;

        float w0 = (1.0f - a0) * T0;
        float w1 = (1.0f - a1) * T1;
        float w2 = (1.0f - a2) * T2;
        float w3 = (1.0f - a3) * T3;

        // unpack 12 floats -> 4 rgb samples
        r = w0 * ca.x + w1 * ca.w + w2 * cb.z + w3 * cc.y;
        g = w0 * ca.y + w1 * cb.x + w2 * cb.w + w3 * cc.z;
        b = w0 * ca.z + w1 * cb.y + w2 * cc.x + w3 * cc.w;
    }

    // ---- warp reduction ----
    #pragma unroll
    for (int off = 16; off >= 1; off >>= 1) {
        r += __shfl_xor_sync(0xffffffffu, r, off);
        g += __shfl_xor_sync(0xffffffffu, g, off);
        b += __shfl_xor_sync(0xffffffffu, b, off);
    }

    if (lane == 0) {
        out[(size_t)ray * 3 + 0] = r;
        out[(size_t)ray * 3 + 1] = g;
        out[(size_t)ray * 3 + 2] = b;
    }
}

extern "C" void kernel_launch(void* const* d_in, const int* in_sizes, int n_in,
                              void* d_out, int out_size)
{
    const float* distance = (const float*)d_in[0];
    const float* color    = (const float*)d_in[1];
    const float* depth    = (const float*)d_in[2];
    float* out = (float*)d_out;

    const int n_rays = in_sizes[0] / 128;   // R = 65536

    // one warp per ray; 256 threads = 8 warps per block
    const int warps_per_block = 8;
    const int blocks = (n_rays + warps_per_block - 1) / warps_per_block;
    volume_sdf_fused_kernel<<<blocks, 256>>>(distance, color, depth, out, n_rays);
}

// round 11
// speedup vs baseline: 1.1712x; 1.0060x over previous
#include <cuda_runtime.h>
#include <cuda_bf16.h>

// VolumeSDFRenderer: R=65536 rays, N=128 samples.
// inputs (metadata order): distance [R,N] f32, color [R,N,3] f32, depth_values [R,N] f32
// output: concat(out_color [R,3], geometry zeros [R,N,3]) as f32.
//
// One warp per ray, TWO-PHASE layout: lane k owns samples {2k, 2k+1} in
// phase 1 (samples 0..63) and {64+2k, 65+2k} in phase 2 (samples 64..127).
//
// Culling (calibrated R9/R10: rel_err scales linearly with T_EPS; 3e-4 ->
// measured 2.04e-4, threshold 1e-3):
//  * per-lane color cull: prefix > -ln(3e-4)=8.112 -> skip 3 color loads+math.
//  * NEW warp-uniform tail cull: if cumsum through sample 63 > 8.112, the
//    whole second half is dead -> skip phase-2 distance/depth/color loads.
//    Every skipped sample already failed the per-lane cull, so this adds NO
//    new error — it only removes the distance/depth bytes of dead tails
//    (~85% of rays -> ~28 MB saved).
// Boundary: sample 63's delta needs depth[64] -> warp-uniform scalar load.
// Exclusive scan via shift-of-inclusive (avoids FAR_DELTA cancellation in the
// last lane). Plain cache policy (streaming hints regressed in R6).

#define ALPHA 10.0f
#define INV_BETA 20.0f      // 1/0.05
#define FAR_DELTA 1e10f
#define CULL_LOG 8.112f     // -ln(3e-4)

__device__ __forceinline__ float sdf_density(float dist) {
    float s = -dist;
    float e = __expf(-INV_BETA * fabsf(s));
    // s<=0: alpha*0.5*exp(s/beta) = 5*e ; s>0: alpha*(1-0.5*exp(-s/beta)) = 10 - 5*e
    return (s <= 0.0f) ? (0.5f * ALPHA * e) : (ALPHA - 0.5f * ALPHA * e);
}

__device__ __forceinline__ float warp_incl_scan(float v, int lane) {
    #pragma unroll
    for (int off = 1; off < 32; off <<= 1) {
        float y = __shfl_up_sync(0xffffffffu, v, off);
        if (lane >= off) v += y;
    }
    return v;
}

__global__ __launch_bounds__(256, 8)
void volume_sdf_fused_kernel(const float* __restrict__ distance,
                             const float* __restrict__ color,
                             const float* __restrict__ depth,
                             float* __restrict__ out,          // full output buffer
                             int n_rays)
{
    const int warp_id = (blockIdx.x * blockDim.x + threadIdx.x) >> 5;
    const int lane    = threadIdx.x & 31;
    if (warp_id >= n_rays) return;
    const int ray = warp_id;

    const size_t base = (size_t)ray * 128;

    // ---- phase-1 loads: samples 0..63 (float2 per lane) + depth[64] ----
    const float2 dA = reinterpret_cast<const float2*>(distance + base)[lane];
    const float2 tA = reinterpret_cast<const float2*>(depth    + base)[lane];
    const float  t64 = depth[base + 64];   // warp-uniform (one sector)

    // ---- zero this ray's geometry slab: 384 floats = 96 float4, coalesced ----
    {
        float4* geo = reinterpret_cast<float4*>(out + (size_t)n_rays * 3 + (size_t)ray * 384);
        const float4 z = make_float4(0.f, 0.f, 0.f, 0.f);
        geo[lane]      = z;
        geo[lane + 32] = z;
        geo[lane + 64] = z;
    }

    // ---- phase-1 deltas / densities ----
    float tnA = __shfl_down_sync(0xffffffffu, tA.x, 1);   // t[2k+2]
    if (lane == 31) tnA = t64;
    float ddA0 = sdf_density(dA.x) * (tA.y - tA.x);
    float ddA1 = sdf_density(dA.y) * (tnA - tA.y);

    // ---- phase-1 scan ----
    float xA = warp_incl_scan(ddA0 + ddA1, lane);
    float exclA = __shfl_up_sync(0xffffffffu, xA, 1);
    if (lane == 0) exclA = 0.0f;
    const float half_total = __shfl_sync(0xffffffffu, xA, 31); // cumsum through sample 63

    float r = 0.0f, g = 0.0f, b = 0.0f;

    // ---- phase-1 color (per-lane cull) ----
    if (exclA < CULL_LOG) {
        const float2* cp = reinterpret_cast<const float2*>(color + (size_t)ray * 384) + lane * 3;
        const float2 f0 = cp[0];
        const float2 f1 = cp[1];
        const float2 f2 = cp[2];
        float T0 = __expf(-exclA);
        float a0 = __expf(-ddA0);
        float a1 = __expf(-ddA1);
        float T1 = T0 * a0;
        float w0 = (1.0f - a0) * T0;
        float w1 = (1.0f - a1) * T1;
        // sample 2k rgb = (f0.x, f0.y, f1.x); sample 2k+1 rgb = (f1.y, f2.x, f2.y)
        r = w0 * f0.x + w1 * f1.y;
        g = w0 * f0.y + w1 * f2.x;
        b = w0 * f1.x + w1 * f2.y;
    }

    // ---- phase 2: samples 64..127, only if the ray isn't opaque yet ----
    // (warp-uniform branch: half_total is broadcast)
    if (half_total < CULL_LOG) {
        const float2 dB = reinterpret_cast<const float2*>(distance + base + 64)[lane];
        const float2 tB = reinterpret_cast<const float2*>(depth    + base + 64)[lane];

        float tnB = __shfl_down_sync(0xffffffffu, tB.x, 1);
        float dltB1 = (lane == 31) ? FAR_DELTA : (tnB - tB.y);
        float ddB0 = sdf_density(dB.x) * (tB.y - tB.x);
        float ddB1 = sdf_density(dB.y) * dltB1;

        float xB = warp_incl_scan(ddB0 + ddB1, lane);
        float exclB = __shfl_up_sync(0xffffffffu, xB, 1);
        if (lane == 0) exclB = 0.0f;
        float ex = half_total + exclB;

        if (ex < CULL_LOG) {
            const float2* cp = reinterpret_cast<const float2*>(color + (size_t)ray * 384 + 192) + lane * 3;
            const float2 f0 = cp[0];
            const float2 f1 = cp[1];
            const float2 f2 = cp[2];
            float T0 = __expf(-ex);
            float a0 = __expf(-ddB0);
            float a1 = __expf(-ddB1);
            float T1 = T0 * a0;
            float w0 = (1.0f - a0) * T0;
            float w1 = (1.0f - a1) * T1;
            r += w0 * f0.x + w1 * f1.y;
            g += w0 * f0.y + w1 * f2.x;
            b += w0 * f1.x + w1 * f2.y;
        }
    }

    // ---- warp reduction ----
    #pragma unroll
    for (int off = 16; off >= 1; off >>= 1) {
        r += __shfl_xor_sync(0xffffffffu, r, off);
        g += __shfl_xor_sync(0xffffffffu, g, off);
        b += __shfl_xor_sync(0xffffffffu, b, off);
    }

    if (lane == 0) {
        out[(size_t)ray * 3 + 0] = r;
        out[(size_t)ray * 3 + 1] = g;
        out[(size_t)ray * 3 + 2] = b;
    }
}

extern "C" void kernel_launch(void* const* d_in, const int* in_sizes, int n_in,
                              void* d_out, int out_size)
{
    const float* distance = (const float*)d_in[0];
    const float* color    = (const float*)d_in[1];
    const float* depth    = (const float*)d_in[2];
    float* out = (float*)d_out;

    const int n_rays = in_sizes[0] / 128;   // R = 65536

    // one warp per ray; 256 threads = 8 warps per block
    const int warps_per_block = 8;
    const int blocks = (n_rays + warps_per_block - 1) / warps_per_block;
    volume_sdf_fused_kernel<<<blocks, 256>>>(distance, color, depth, out, n_rays);
}